// round 3
// baseline (speedup 1.0000x reference)
#include <cuda_runtime.h>
#include <cuda_bf16.h>
#include <math.h>
#include <stdint.h>

// Problem constants
#define BB 4
#define TT 2048
#define CC 1024
#define HH 16
#define HD 64
#define MROWS (BB * TT)          // 8192
#define N_QKV (3 * CC)           // 3072

// Scratch (static device globals: allocation-free)
__device__ float g_q[BB * HH * TT * HD];   // [b*H+h][T][hd]
__device__ float g_k[BB * HH * TT * HD];
__device__ float g_v[BB * HH * TT * HD];
__device__ float g_att[BB * TT * CC];      // [B,T,C] pre-projection

// ---------------------------------------------------------------------------
// mma.sync m16n8k16 bf16 (portable tensor path; no tcgen05 on this target)
// ---------------------------------------------------------------------------
__device__ __forceinline__ void mma16816(float* c, const uint32_t* a,
                                         uint32_t b0, uint32_t b1) {
    asm volatile(
        "mma.sync.aligned.m16n8k16.row.col.f32.bf16.bf16.f32 "
        "{%0,%1,%2,%3}, {%4,%5,%6,%7}, {%8,%9}, {%0,%1,%2,%3};"
        : "+f"(c[0]), "+f"(c[1]), "+f"(c[2]), "+f"(c[3])
        : "r"(a[0]), "r"(a[1]), "r"(a[2]), "r"(a[3]), "r"(b0), "r"(b1));
}

// ---------------------------------------------------------------------------
// Split-bf16 NT GEMM: C[m,n] = sum_k A[m,k]*B[n,k], fp32-accurate.
// 128x128 CTA tile, K-chunk 32, 256 threads (8 warps, 4x2), warp tile 32x64.
// smem row stride 40 bf16 (80B) -> conflict-free b32 fragment loads.
// EPI=0: scatter into g_q/g_k/g_v.  EPI=1: out = C + bias (A from g_att).
// ---------------------------------------------------------------------------
#define APAD_B 80                          // bytes per smem row (40 bf16)
#define TILE_B (128 * APAD_B)              // 10240 B: one 128x32 bf16 tile
#define BUF_B  (4 * TILE_B)                // AH, AL, BH, BL
#define GEMM_SMEM (2 * BUF_B)              // 81920 B (also covers Ds 128x132 f32)
#define NCHUNK (CC / 32)                   // 32

template <int EPI>
__global__ __launch_bounds__(256) void tc_gemm(const float* __restrict__ Ain,
                                               const float* __restrict__ Bw,
                                               const float* __restrict__ bias,
                                               float* __restrict__ out) {
    extern __shared__ char smc[];
    const float* A = (EPI == 1) ? g_att : Ain;
    const int tid = threadIdx.x;
    const int m0 = blockIdx.y * 128;
    const int n0 = blockIdx.x * 128;
    const int wid = tid >> 5;
    const int lane = tid & 31;
    const int gid = lane >> 2;             // 0..7
    const int tig = lane & 3;              // 0..3
    const int wm = wid & 3;                // m block (32 rows)
    const int wn = wid >> 2;               // n block (64 cols)

    float acc[2][8][4];
#pragma unroll
    for (int i = 0; i < 2; i++)
#pragma unroll
        for (int j = 0; j < 8; j++)
#pragma unroll
            for (int q = 0; q < 4; q++) acc[i][j][q] = 0.f;

    float4 sa[4], sb[4];

    // ---- stage: global loads for chunk at kk into regs
    auto ldg = [&](int kk) {
#pragma unroll
        for (int l = 0; l < 4; l++) {
            int e = l * 256 + tid;         // 0..1023
            int r = e >> 3;                // 0..127
            int c4 = (e & 7) * 4;          // 0..28
            sa[l] = *(const float4*)(A + (size_t)(m0 + r) * CC + kk + c4);
            sb[l] = *(const float4*)(Bw + (size_t)(n0 + r) * CC + kk + c4);
        }
    };
    // ---- stage: split hi/lo and store to smem buffer
    auto sts = [&](char* buf) {
#pragma unroll
        for (int l = 0; l < 4; l++) {
            int e = l * 256 + tid;
            int r = e >> 3;
            int c4 = (e & 7) * 4;
            uint32_t off = (uint32_t)(r * APAD_B + c4 * 2);
            float4 va = sa[l];
            __nv_bfloat162 h01 = __floats2bfloat162_rn(va.x, va.y);
            __nv_bfloat162 h23 = __floats2bfloat162_rn(va.z, va.w);
            __nv_bfloat162 l01 = __floats2bfloat162_rn(va.x - __bfloat162float(h01.x),
                                                       va.y - __bfloat162float(h01.y));
            __nv_bfloat162 l23 = __floats2bfloat162_rn(va.z - __bfloat162float(h23.x),
                                                       va.w - __bfloat162float(h23.y));
            *(uint2*)(buf + off) =
                make_uint2(reinterpret_cast<uint32_t&>(h01), reinterpret_cast<uint32_t&>(h23));
            *(uint2*)(buf + TILE_B + off) =
                make_uint2(reinterpret_cast<uint32_t&>(l01), reinterpret_cast<uint32_t&>(l23));
            float4 vb = sb[l];
            __nv_bfloat162 g01 = __floats2bfloat162_rn(vb.x, vb.y);
            __nv_bfloat162 g23 = __floats2bfloat162_rn(vb.z, vb.w);
            __nv_bfloat162 m01 = __floats2bfloat162_rn(vb.x - __bfloat162float(g01.x),
                                                       vb.y - __bfloat162float(g01.y));
            __nv_bfloat162 m23 = __floats2bfloat162_rn(vb.z - __bfloat162float(g23.x),
                                                       vb.w - __bfloat162float(g23.y));
            *(uint2*)(buf + 2 * TILE_B + off) =
                make_uint2(reinterpret_cast<uint32_t&>(g01), reinterpret_cast<uint32_t&>(g23));
            *(uint2*)(buf + 3 * TILE_B + off) =
                make_uint2(reinterpret_cast<uint32_t&>(m01), reinterpret_cast<uint32_t&>(m23));
        }
    };
    // ---- compute one K-chunk (k=32) from smem buffer
    auto compute = [&](const char* buf) {
#pragma unroll
        for (int ks = 0; ks < 2; ks++) {
            uint32_t ah[2][4], al[2][4];
#pragma unroll
            for (int i = 0; i < 2; i++) {
                int row = wm * 32 + i * 16 + gid;
                uint32_t o = (uint32_t)(row * APAD_B + ks * 32 + tig * 4);
                ah[i][0] = *(const uint32_t*)(buf + o);
                ah[i][1] = *(const uint32_t*)(buf + o + 8 * APAD_B);
                ah[i][2] = *(const uint32_t*)(buf + o + 16);
                ah[i][3] = *(const uint32_t*)(buf + o + 8 * APAD_B + 16);
                al[i][0] = *(const uint32_t*)(buf + TILE_B + o);
                al[i][1] = *(const uint32_t*)(buf + TILE_B + o + 8 * APAD_B);
                al[i][2] = *(const uint32_t*)(buf + TILE_B + o + 16);
                al[i][3] = *(const uint32_t*)(buf + TILE_B + o + 8 * APAD_B + 16);
            }
#pragma unroll
            for (int j = 0; j < 8; j++) {
                int n = wn * 64 + j * 8 + gid;
                uint32_t o = (uint32_t)(n * APAD_B + ks * 32 + tig * 4);
                uint32_t bh0 = *(const uint32_t*)(buf + 2 * TILE_B + o);
                uint32_t bh1 = *(const uint32_t*)(buf + 2 * TILE_B + o + 16);
                uint32_t bl0 = *(const uint32_t*)(buf + 3 * TILE_B + o);
                uint32_t bl1 = *(const uint32_t*)(buf + 3 * TILE_B + o + 16);
#pragma unroll
                for (int i = 0; i < 2; i++) {
                    mma16816(acc[i][j], ah[i], bh0, bh1);
                    mma16816(acc[i][j], ah[i], bl0, bl1);
                    mma16816(acc[i][j], al[i], bh0, bh1);
                }
            }
        }
    };

    // ---- pipeline: one barrier per chunk
    ldg(0);
    sts(smc);
    __syncthreads();
    for (int c = 0; c < NCHUNK; c++) {
        char* cur = smc + (size_t)(c & 1) * BUF_B;
        char* nxt = smc + (size_t)((c + 1) & 1) * BUF_B;
        if (c + 1 < NCHUNK) ldg((c + 1) * 32);
        compute(cur);
        if (c + 1 < NCHUNK) sts(nxt);      // nxt last read in chunk c-1 (done)
        __syncthreads();
    }

    // ---- epilogue: fragments -> smem staging -> coalesced global writes
    float* Ds = (float*)smc;               // 128 x 132 f32 = 67584 B < 81920 B
#pragma unroll
    for (int i = 0; i < 2; i++) {
        int rr = wm * 32 + i * 16 + gid;
#pragma unroll
        for (int j = 0; j < 8; j++) {
            int cc = wn * 64 + j * 8 + tig * 2;
            *(float2*)&Ds[rr * 132 + cc]       = make_float2(acc[i][j][0], acc[i][j][1]);
            *(float2*)&Ds[(rr + 8) * 132 + cc] = make_float2(acc[i][j][2], acc[i][j][3]);
        }
    }
    __syncthreads();

#pragma unroll 4
    for (int ll = 0; ll < 64; ll++) {
        int flat = ll * 256 + tid;
        int n = flat & 127;
        int m = flat >> 7;
        float v = Ds[m * 132 + n];
        if (EPI == 0) {
            int gm = m0 + m; int b = gm >> 11; int t = gm & 2047;
            int gn = n0 + n; int h = gn / 192; int rr = gn - h * 192;
            int part = rr >> 6; int d = rr & 63;
            float* dst = (part == 0) ? g_q : (part == 1) ? g_k : g_v;
            dst[(((size_t)(b * HH + h)) * TT + t) * HD + d] = v;
        } else {
            int gm = m0 + m; int gn = n0 + n;
            out[(size_t)gm * CC + gn] = v + bias[gn];
        }
    }
}

// ---------------------------------------------------------------------------
// Flash attention, fp32 (unchanged). BM=128, BN=64, hd=64, 128 thr.
// ---------------------------------------------------------------------------
#define ATT_SMEM_FLOATS (64 * 132 + 64 * 68 + 64 * 68 + 64 * 132)
#define ATT_SMEM_BYTES (ATT_SMEM_FLOATS * 4)

__global__ __launch_bounds__(128) void attn_kernel() {
    extern __shared__ float smf[];
    float(*Qst)[132] = (float(*)[132])smf;
    float(*Kst)[68]  = (float(*)[68])(smf + 64 * 132);
    float(*Vs)[68]   = (float(*)[68])(smf + 64 * 132 + 64 * 68);
    float(*Pst)[132] = (float(*)[132])(smf + 64 * 132 + 2 * 64 * 68);

    const int tid = threadIdx.x;
    const int bh = blockIdx.y;
    const int q0 = blockIdx.x * 128;
    const float* Qb = g_q + (size_t)bh * TT * HD;
    const float* Kb = g_k + (size_t)bh * TT * HD;
    const float* Vb = g_v + (size_t)bh * TT * HD;
    const int tx = tid & 7;
    const int ty = tid >> 3;

#pragma unroll
    for (int l = 0; l < 16; l++) {
        int e = l * 128 + tid;
        int r = e >> 4;
        int c4 = (e & 15) * 4;
        float4 v = *(const float4*)(Qb + (size_t)(q0 + r) * HD + c4);
        Qst[c4 + 0][r] = v.x; Qst[c4 + 1][r] = v.y;
        Qst[c4 + 2][r] = v.z; Qst[c4 + 3][r] = v.w;
    }

    float o[8][8];
#pragma unroll
    for (int i = 0; i < 8; i++)
#pragma unroll
        for (int j = 0; j < 8; j++) o[i][j] = 0.f;
    float mr[8], lr[8];
#pragma unroll
    for (int i = 0; i < 8; i++) { mr[i] = -1e30f; lr[i] = 0.f; }

    const int jmax = (q0 >> 6) + 2;

    for (int j = 0; j < jmax; j++) {
        const int k0 = j * 64;
        __syncthreads();
#pragma unroll
        for (int l = 0; l < 8; l++) {
            int e = l * 128 + tid;
            int r = e >> 4;
            int c4 = (e & 15) * 4;
            float4 kv = *(const float4*)(Kb + (size_t)(k0 + r) * HD + c4);
            Kst[c4 + 0][r] = kv.x; Kst[c4 + 1][r] = kv.y;
            Kst[c4 + 2][r] = kv.z; Kst[c4 + 3][r] = kv.w;
            float4 vv = *(const float4*)(Vb + (size_t)(k0 + r) * HD + c4);
            *(float4*)&Vs[r][c4] = vv;
        }
        __syncthreads();

        float s[8][8];
#pragma unroll
        for (int i = 0; i < 8; i++)
#pragma unroll
            for (int jj = 0; jj < 8; jj++) s[i][jj] = 0.f;
#pragma unroll 8
        for (int d = 0; d < 64; d++) {
            float qv[8], kv[8];
            *(float4*)&qv[0] = *(const float4*)&Qst[d][ty * 8];
            *(float4*)&qv[4] = *(const float4*)&Qst[d][ty * 8 + 4];
            *(float4*)&kv[0] = *(const float4*)&Kst[d][tx * 8];
            *(float4*)&kv[4] = *(const float4*)&Kst[d][tx * 8 + 4];
#pragma unroll
            for (int i = 0; i < 8; i++)
#pragma unroll
                for (int jj = 0; jj < 8; jj++) s[i][jj] += qv[i] * kv[jj];
        }
#pragma unroll
        for (int i = 0; i < 8; i++)
#pragma unroll
            for (int jj = 0; jj < 8; jj++) s[i][jj] *= 0.125f;

        if (k0 + 63 > q0) {
#pragma unroll
            for (int i = 0; i < 8; i++) {
                int qg = q0 + ty * 8 + i;
#pragma unroll
                for (int jj = 0; jj < 8; jj++) {
                    int kg = k0 + tx * 8 + jj;
                    if (kg > qg) s[i][jj] = -1e30f;
                }
            }
        }

#pragma unroll
        for (int i = 0; i < 8; i++) {
            float mx = s[i][0];
#pragma unroll
            for (int jj = 1; jj < 8; jj++) mx = fmaxf(mx, s[i][jj]);
            mx = fmaxf(mx, __shfl_xor_sync(0xffffffffu, mx, 1));
            mx = fmaxf(mx, __shfl_xor_sync(0xffffffffu, mx, 2));
            mx = fmaxf(mx, __shfl_xor_sync(0xffffffffu, mx, 4));
            float mnew = fmaxf(mr[i], mx);
            float alpha = __expf(mr[i] - mnew);
            float sum = 0.f;
#pragma unroll
            for (int jj = 0; jj < 8; jj++) {
                float p = __expf(s[i][jj] - mnew);
                s[i][jj] = p;
                sum += p;
            }
            sum += __shfl_xor_sync(0xffffffffu, sum, 1);
            sum += __shfl_xor_sync(0xffffffffu, sum, 2);
            sum += __shfl_xor_sync(0xffffffffu, sum, 4);
            lr[i] = lr[i] * alpha + sum;
            mr[i] = mnew;
#pragma unroll
            for (int jj = 0; jj < 8; jj++) o[i][jj] *= alpha;
#pragma unroll
            for (int jj = 0; jj < 8; jj++)
                Pst[tx * 8 + jj][ty * 8 + i] = s[i][jj];
        }
        __syncthreads();

#pragma unroll 8
        for (int k = 0; k < 64; k++) {
            float pv[8], vv[8];
            *(float4*)&pv[0] = *(const float4*)&Pst[k][ty * 8];
            *(float4*)&pv[4] = *(const float4*)&Pst[k][ty * 8 + 4];
            *(float4*)&vv[0] = *(const float4*)&Vs[k][tx * 8];
            *(float4*)&vv[4] = *(const float4*)&Vs[k][tx * 8 + 4];
#pragma unroll
            for (int i = 0; i < 8; i++)
#pragma unroll
                for (int jj = 0; jj < 8; jj++) o[i][jj] += pv[i] * vv[jj];
        }
    }

    const int b = bh >> 4;
    const int h = bh & 15;
#pragma unroll
    for (int i = 0; i < 8; i++) {
        int t = q0 + ty * 8 + i;
        float inv = 1.f / lr[i];
#pragma unroll
        for (int jj = 0; jj < 8; jj++) {
            g_att[((size_t)(b * TT + t)) * CC + h * HD + tx * 8 + jj] = o[i][jj] * inv;
        }
    }
}

// ---------------------------------------------------------------------------

extern "C" void kernel_launch(void* const* d_in, const int* in_sizes, int n_in,
                              void* d_out, int out_size) {
    const float* x      = (const float*)d_in[0];
    const float* w_qkv  = (const float*)d_in[1];
    const float* w_proj = (const float*)d_in[2];
    const float* b_proj = (const float*)d_in[3];
    float* out = (float*)d_out;

    cudaFuncSetAttribute(tc_gemm<0>, cudaFuncAttributeMaxDynamicSharedMemorySize, GEMM_SMEM);
    cudaFuncSetAttribute(tc_gemm<1>, cudaFuncAttributeMaxDynamicSharedMemorySize, GEMM_SMEM);
    cudaFuncSetAttribute(attn_kernel, cudaFuncAttributeMaxDynamicSharedMemorySize, ATT_SMEM_BYTES);

    tc_gemm<0><<<dim3(N_QKV / 128, MROWS / 128), 256, GEMM_SMEM>>>(x, w_qkv, nullptr, nullptr);
    attn_kernel<<<dim3(TT / 128, BB * HH), 128, ATT_SMEM_BYTES>>>();
    tc_gemm<1><<<dim3(CC / 128, MROWS / 128), 256, GEMM_SMEM>>>(nullptr, w_proj, b_proj, out);
}

// round 4
// speedup vs baseline: 2.4609x; 2.4609x over previous
#include <cuda_runtime.h>
#include <cuda_bf16.h>
#include <cuda_fp16.h>
#include <math.h>
#include <stdint.h>

// Problem constants
#define BB 4
#define TT 2048
#define CC 1024
#define HH 16
#define HD 64
#define MROWS (BB * TT)          // 8192
#define N_QKV (3 * CC)           // 3072

// Scratch (static device globals: allocation-free)
__device__ float g_q[BB * HH * TT * HD];   // [b*H+h][T][hd]
__device__ float g_k[BB * HH * TT * HD];
__device__ float g_v[BB * HH * TT * HD];
__device__ float g_att[BB * TT * CC];      // [B,T,C] pre-projection

// ---------------------------------------------------------------------------
// mma.sync m16n8k16 (portable tensor path; tcgen05 PTX is rejected by the
// harness's sm_103 (non-'a') ptxas target)
// ---------------------------------------------------------------------------
__device__ __forceinline__ void mma16816(float* c, const uint32_t* a,
                                         uint32_t b0, uint32_t b1) {
    asm volatile(
        "mma.sync.aligned.m16n8k16.row.col.f32.bf16.bf16.f32 "
        "{%0,%1,%2,%3}, {%4,%5,%6,%7}, {%8,%9}, {%0,%1,%2,%3};"
        : "+f"(c[0]), "+f"(c[1]), "+f"(c[2]), "+f"(c[3])
        : "r"(a[0]), "r"(a[1]), "r"(a[2]), "r"(a[3]), "r"(b0), "r"(b1));
}
__device__ __forceinline__ void mma16816h(float* c, const uint32_t* a,
                                          uint32_t b0, uint32_t b1) {
    asm volatile(
        "mma.sync.aligned.m16n8k16.row.col.f32.f16.f16.f32 "
        "{%0,%1,%2,%3}, {%4,%5,%6,%7}, {%8,%9}, {%0,%1,%2,%3};"
        : "+f"(c[0]), "+f"(c[1]), "+f"(c[2]), "+f"(c[3])
        : "r"(a[0]), "r"(a[1]), "r"(a[2]), "r"(a[3]), "r"(b0), "r"(b1));
}

__device__ __forceinline__ uint32_t h2u(__half2 h) {
    return *reinterpret_cast<uint32_t*>(&h);
}

// ---------------------------------------------------------------------------
// Split-bf16 NT GEMM (unchanged from R3): C[m,n] = sum_k A[m,k]*B[n,k].
// ---------------------------------------------------------------------------
#define APAD_B 80
#define TILE_B (128 * APAD_B)
#define BUF_B  (4 * TILE_B)
#define GEMM_SMEM (2 * BUF_B)
#define NCHUNK (CC / 32)

template <int EPI>
__global__ __launch_bounds__(256) void tc_gemm(const float* __restrict__ Ain,
                                               const float* __restrict__ Bw,
                                               const float* __restrict__ bias,
                                               float* __restrict__ out) {
    extern __shared__ char smc[];
    const float* A = (EPI == 1) ? g_att : Ain;
    const int tid = threadIdx.x;
    const int m0 = blockIdx.y * 128;
    const int n0 = blockIdx.x * 128;
    const int wid = tid >> 5;
    const int lane = tid & 31;
    const int gid = lane >> 2;
    const int tig = lane & 3;
    const int wm = wid & 3;
    const int wn = wid >> 2;

    float acc[2][8][4];
#pragma unroll
    for (int i = 0; i < 2; i++)
#pragma unroll
        for (int j = 0; j < 8; j++)
#pragma unroll
            for (int q = 0; q < 4; q++) acc[i][j][q] = 0.f;

    float4 sa[4], sb[4];

    auto ldg = [&](int kk) {
#pragma unroll
        for (int l = 0; l < 4; l++) {
            int e = l * 256 + tid;
            int r = e >> 3;
            int c4 = (e & 7) * 4;
            sa[l] = *(const float4*)(A + (size_t)(m0 + r) * CC + kk + c4);
            sb[l] = *(const float4*)(Bw + (size_t)(n0 + r) * CC + kk + c4);
        }
    };
    auto sts = [&](char* buf) {
#pragma unroll
        for (int l = 0; l < 4; l++) {
            int e = l * 256 + tid;
            int r = e >> 3;
            int c4 = (e & 7) * 4;
            uint32_t off = (uint32_t)(r * APAD_B + c4 * 2);
            float4 va = sa[l];
            __nv_bfloat162 h01 = __floats2bfloat162_rn(va.x, va.y);
            __nv_bfloat162 h23 = __floats2bfloat162_rn(va.z, va.w);
            __nv_bfloat162 l01 = __floats2bfloat162_rn(va.x - __bfloat162float(h01.x),
                                                       va.y - __bfloat162float(h01.y));
            __nv_bfloat162 l23 = __floats2bfloat162_rn(va.z - __bfloat162float(h23.x),
                                                       va.w - __bfloat162float(h23.y));
            *(uint2*)(buf + off) =
                make_uint2(reinterpret_cast<uint32_t&>(h01), reinterpret_cast<uint32_t&>(h23));
            *(uint2*)(buf + TILE_B + off) =
                make_uint2(reinterpret_cast<uint32_t&>(l01), reinterpret_cast<uint32_t&>(l23));
            float4 vb = sb[l];
            __nv_bfloat162 g01 = __floats2bfloat162_rn(vb.x, vb.y);
            __nv_bfloat162 g23 = __floats2bfloat162_rn(vb.z, vb.w);
            __nv_bfloat162 m01 = __floats2bfloat162_rn(vb.x - __bfloat162float(g01.x),
                                                       vb.y - __bfloat162float(g01.y));
            __nv_bfloat162 m23 = __floats2bfloat162_rn(vb.z - __bfloat162float(g23.x),
                                                       vb.w - __bfloat162float(g23.y));
            *(uint2*)(buf + 2 * TILE_B + off) =
                make_uint2(reinterpret_cast<uint32_t&>(g01), reinterpret_cast<uint32_t&>(g23));
            *(uint2*)(buf + 3 * TILE_B + off) =
                make_uint2(reinterpret_cast<uint32_t&>(m01), reinterpret_cast<uint32_t&>(m23));
        }
    };
    auto compute = [&](const char* buf) {
#pragma unroll
        for (int ks = 0; ks < 2; ks++) {
            uint32_t ah[2][4], al[2][4];
#pragma unroll
            for (int i = 0; i < 2; i++) {
                int row = wm * 32 + i * 16 + gid;
                uint32_t o = (uint32_t)(row * APAD_B + ks * 32 + tig * 4);
                ah[i][0] = *(const uint32_t*)(buf + o);
                ah[i][1] = *(const uint32_t*)(buf + o + 8 * APAD_B);
                ah[i][2] = *(const uint32_t*)(buf + o + 16);
                ah[i][3] = *(const uint32_t*)(buf + o + 8 * APAD_B + 16);
                al[i][0] = *(const uint32_t*)(buf + TILE_B + o);
                al[i][1] = *(const uint32_t*)(buf + TILE_B + o + 8 * APAD_B);
                al[i][2] = *(const uint32_t*)(buf + TILE_B + o + 16);
                al[i][3] = *(const uint32_t*)(buf + TILE_B + o + 8 * APAD_B + 16);
            }
#pragma unroll
            for (int j = 0; j < 8; j++) {
                int n = wn * 64 + j * 8 + gid;
                uint32_t o = (uint32_t)(n * APAD_B + ks * 32 + tig * 4);
                uint32_t bh0 = *(const uint32_t*)(buf + 2 * TILE_B + o);
                uint32_t bh1 = *(const uint32_t*)(buf + 2 * TILE_B + o + 16);
                uint32_t bl0 = *(const uint32_t*)(buf + 3 * TILE_B + o);
                uint32_t bl1 = *(const uint32_t*)(buf + 3 * TILE_B + o + 16);
#pragma unroll
                for (int i = 0; i < 2; i++) {
                    mma16816(acc[i][j], ah[i], bh0, bh1);
                    mma16816(acc[i][j], ah[i], bl0, bl1);
                    mma16816(acc[i][j], al[i], bh0, bh1);
                }
            }
        }
    };

    ldg(0);
    sts(smc);
    __syncthreads();
    for (int c = 0; c < NCHUNK; c++) {
        char* cur = smc + (size_t)(c & 1) * BUF_B;
        char* nxt = smc + (size_t)((c + 1) & 1) * BUF_B;
        if (c + 1 < NCHUNK) ldg((c + 1) * 32);
        compute(cur);
        if (c + 1 < NCHUNK) sts(nxt);
        __syncthreads();
    }

    float* Ds = (float*)smc;
#pragma unroll
    for (int i = 0; i < 2; i++) {
        int rr = wm * 32 + i * 16 + gid;
#pragma unroll
        for (int j = 0; j < 8; j++) {
            int cc = wn * 64 + j * 8 + tig * 2;
            *(float2*)&Ds[rr * 132 + cc]       = make_float2(acc[i][j][0], acc[i][j][1]);
            *(float2*)&Ds[(rr + 8) * 132 + cc] = make_float2(acc[i][j][2], acc[i][j][3]);
        }
    }
    __syncthreads();

#pragma unroll 4
    for (int ll = 0; ll < 64; ll++) {
        int flat = ll * 256 + tid;
        int n = flat & 127;
        int m = flat >> 7;
        float v = Ds[m * 132 + n];
        if (EPI == 0) {
            int gm = m0 + m; int b = gm >> 11; int t = gm & 2047;
            int gn = n0 + n; int h = gn / 192; int rr = gn - h * 192;
            int part = rr >> 6; int d = rr & 63;
            float* dst = (part == 0) ? g_q : (part == 1) ? g_k : g_v;
            dst[(((size_t)(b * HH + h)) * TT + t) * HD + d] = v;
        } else {
            int gm = m0 + m; int gn = n0 + n;
            out[(size_t)gm * CC + gn] = v + bias[gn];
        }
    }
}

// ---------------------------------------------------------------------------
// Flash attention, split-fp16 mma.sync. BM=128 (8 warps x 16 rows), BN=64.
// S/O accs in regs; P fragments repacked from S accs (no smem round trip).
// Smem: Kh/Kl [s][d] row-major, Vh/Vl [d][s] transposed; row stride 144B
// -> conflict-free b-fragment loads (bank = 4*gid + tig + 8*ks).
// ---------------------------------------------------------------------------
#define AT_ROW 144
#define AT_TILE (64 * AT_ROW)
#define ATT_SMEM_BYTES (4 * AT_TILE)       // 36864

__global__ __launch_bounds__(256) void attn_kernel() {
    extern __shared__ char smc[];
    char* Kh = smc;
    char* Kl = smc + AT_TILE;
    char* Vh = smc + 2 * AT_TILE;          // transposed [d][s]
    char* Vl = smc + 3 * AT_TILE;

    const int tid = threadIdx.x;
    const int bh = blockIdx.y;
    const int q0 = blockIdx.x * 128;
    const float* Qb = g_q + (size_t)bh * TT * HD;
    const float* Kb = g_k + (size_t)bh * TT * HD;
    const float* Vb = g_v + (size_t)bh * TT * HD;
    const int wid = tid >> 5;
    const int lane = tid & 31;
    const int gid = lane >> 2;
    const int tig = lane & 3;
    const int r0 = q0 + wid * 16 + gid;    // q row for c0/c1; r0+8 for c2/c3

    // ---- Q fragments (hi/lo fp16), direct from gmem, once per CTA
    uint32_t qh[4][4], ql[4][4];
#pragma unroll
    for (int ks = 0; ks < 4; ks++) {
#pragma unroll
        for (int hv = 0; hv < 2; hv++) {
#pragma unroll
            for (int rr = 0; rr < 2; rr++) {
                float2 v = *(const float2*)(Qb + (size_t)(r0 + rr * 8) * HD +
                                            ks * 16 + hv * 8 + tig * 2);
                __half2 h = __floats2half2_rn(v.x, v.y);
                float2 hf = __half22float2(h);
                __half2 l = __floats2half2_rn(v.x - hf.x, v.y - hf.y);
                qh[ks][hv * 2 + rr] = h2u(h);
                ql[ks][hv * 2 + rr] = h2u(l);
            }
        }
    }

    float oacc[8][4];
#pragma unroll
    for (int j = 0; j < 8; j++)
#pragma unroll
        for (int q = 0; q < 4; q++) oacc[j][q] = 0.f;
    float mr0 = -1e30f, mr1 = -1e30f, lr0 = 0.f, lr1 = 0.f;

    float4 kst[4], vst[4];
    auto ldgKV = [&](int k0) {
#pragma unroll
        for (int l = 0; l < 4; l++) {
            int e = l * 256 + tid;
            int r = e >> 4, c4 = (e & 15) * 4;
            kst[l] = *(const float4*)(Kb + (size_t)(k0 + r) * HD + c4);
            int s = e & 63, cb = (e >> 6) * 4;
            vst[l] = *(const float4*)(Vb + (size_t)(k0 + s) * HD + cb);
        }
    };
    auto stsKV = [&]() {
#pragma unroll
        for (int l = 0; l < 4; l++) {
            int e = l * 256 + tid;
            int r = e >> 4, c4 = (e & 15) * 4;
            float4 kv = kst[l];
            __half2 h01 = __floats2half2_rn(kv.x, kv.y);
            __half2 h23 = __floats2half2_rn(kv.z, kv.w);
            float2 f01 = __half22float2(h01);
            float2 f23 = __half22float2(h23);
            __half2 l01 = __floats2half2_rn(kv.x - f01.x, kv.y - f01.y);
            __half2 l23 = __floats2half2_rn(kv.z - f23.x, kv.w - f23.y);
            *(uint2*)(Kh + r * AT_ROW + c4 * 2) = make_uint2(h2u(h01), h2u(h23));
            *(uint2*)(Kl + r * AT_ROW + c4 * 2) = make_uint2(h2u(l01), h2u(l23));
            int s = e & 63, cb = (e >> 6) * 4;
            float4 vv = vst[l];
            float vals[4] = {vv.x, vv.y, vv.z, vv.w};
#pragma unroll
            for (int k = 0; k < 4; k++) {
                __half hh = __float2half_rn(vals[k]);
                __half hl = __float2half_rn(vals[k] - __half2float(hh));
                *(__half*)(Vh + (cb + k) * AT_ROW + s * 2) = hh;
                *(__half*)(Vl + (cb + k) * AT_ROW + s * 2) = hl;
            }
        }
    };

    const int jmax = (q0 >> 6) + 2;
    ldgKV(0);
    for (int c = 0; c < jmax; c++) {
        stsKV();
        __syncthreads();
        if (c + 1 < jmax) ldgKV((c + 1) * 64);

        // ---- S = Q K^T (split: qh*kh + qh*kl + ql*kh)
        float s[8][4];
#pragma unroll
        for (int j = 0; j < 8; j++)
#pragma unroll
            for (int q = 0; q < 4; q++) s[j][q] = 0.f;
#pragma unroll
        for (int ks = 0; ks < 4; ks++) {
#pragma unroll
            for (int j = 0; j < 8; j++) {
                uint32_t o = (uint32_t)((8 * j + gid) * AT_ROW + ks * 32 + tig * 4);
                uint32_t bh0 = *(const uint32_t*)(Kh + o);
                uint32_t bh1 = *(const uint32_t*)(Kh + o + 16);
                uint32_t bl0 = *(const uint32_t*)(Kl + o);
                uint32_t bl1 = *(const uint32_t*)(Kl + o + 16);
                mma16816h(s[j], qh[ks], bh0, bh1);
                mma16816h(s[j], qh[ks], bl0, bl1);
                mma16816h(s[j], ql[ks], bh0, bh1);
            }
        }

        // ---- scale + causal mask (only needed on the last two blocks)
        const int k0 = c * 64;
#pragma unroll
        for (int j = 0; j < 8; j++)
#pragma unroll
            for (int q = 0; q < 4; q++) s[j][q] *= 0.125f;
        if (c >= jmax - 2) {
#pragma unroll
            for (int j = 0; j < 8; j++) {
                int col = k0 + 8 * j + 2 * tig;
                if (col > r0)          s[j][0] = -1e30f;
                if (col + 1 > r0)      s[j][1] = -1e30f;
                if (col > r0 + 8)      s[j][2] = -1e30f;
                if (col + 1 > r0 + 8)  s[j][3] = -1e30f;
            }
        }

        // ---- online softmax (2 rows per thread; reduce over tig lanes)
        float pm0 = -1e30f, pm1 = -1e30f;
#pragma unroll
        for (int j = 0; j < 8; j++) {
            pm0 = fmaxf(pm0, fmaxf(s[j][0], s[j][1]));
            pm1 = fmaxf(pm1, fmaxf(s[j][2], s[j][3]));
        }
        pm0 = fmaxf(pm0, __shfl_xor_sync(0xffffffffu, pm0, 1));
        pm0 = fmaxf(pm0, __shfl_xor_sync(0xffffffffu, pm0, 2));
        pm1 = fmaxf(pm1, __shfl_xor_sync(0xffffffffu, pm1, 1));
        pm1 = fmaxf(pm1, __shfl_xor_sync(0xffffffffu, pm1, 2));
        float mn0 = fmaxf(mr0, pm0), mn1 = fmaxf(mr1, pm1);
        float a0 = __expf(mr0 - mn0), a1 = __expf(mr1 - mn1);
        float sum0 = 0.f, sum1 = 0.f;
#pragma unroll
        for (int j = 0; j < 8; j++) {
            s[j][0] = __expf(s[j][0] - mn0);
            s[j][1] = __expf(s[j][1] - mn0);
            s[j][2] = __expf(s[j][2] - mn1);
            s[j][3] = __expf(s[j][3] - mn1);
            sum0 += s[j][0] + s[j][1];
            sum1 += s[j][2] + s[j][3];
        }
        sum0 += __shfl_xor_sync(0xffffffffu, sum0, 1);
        sum0 += __shfl_xor_sync(0xffffffffu, sum0, 2);
        sum1 += __shfl_xor_sync(0xffffffffu, sum1, 1);
        sum1 += __shfl_xor_sync(0xffffffffu, sum1, 2);
        lr0 = lr0 * a0 + sum0;
        lr1 = lr1 * a1 + sum1;
        mr0 = mn0; mr1 = mn1;
#pragma unroll
        for (int j = 0; j < 8; j++) {
            oacc[j][0] *= a0; oacc[j][1] *= a0;
            oacc[j][2] *= a1; oacc[j][3] *= a1;
        }

        // ---- pack P fragments (hi/lo) straight from S accs
        uint32_t pah[4][4], pal[4][4];
#pragma unroll
        for (int ks = 0; ks < 4; ks++) {
            int j0 = 2 * ks, j1 = 2 * ks + 1;
#pragma unroll
            for (int part = 0; part < 4; part++) {
                int jj = (part < 2) ? j0 : j1;
                int qa = (part & 1) * 2;      // 0 -> c0,c1 ; 1 -> c2,c3
                float x = s[jj][qa], y = s[jj][qa + 1];
                __half2 h = __floats2half2_rn(x, y);
                float2 hf = __half22float2(h);
                __half2 l = __floats2half2_rn(x - hf.x, y - hf.y);
                pah[ks][part] = h2u(h);
                pal[ks][part] = h2u(l);
            }
        }

        // ---- O += P V (split: ph*vh + ph*vl + pl*vh)
#pragma unroll
        for (int ks = 0; ks < 4; ks++) {
#pragma unroll
            for (int j = 0; j < 8; j++) {
                uint32_t o = (uint32_t)((8 * j + gid) * AT_ROW + ks * 32 + tig * 4);
                uint32_t vh0 = *(const uint32_t*)(Vh + o);
                uint32_t vh1 = *(const uint32_t*)(Vh + o + 16);
                uint32_t vl0 = *(const uint32_t*)(Vl + o);
                uint32_t vl1 = *(const uint32_t*)(Vl + o + 16);
                mma16816h(oacc[j], pah[ks], vh0, vh1);
                mma16816h(oacc[j], pah[ks], vl0, vl1);
                mma16816h(oacc[j], pal[ks], vh0, vh1);
            }
        }
        __syncthreads();
    }

    // ---- epilogue: normalize, write g_att [B,T,C], C-col = h*64 + d
    const int b = bh >> 4;
    const int h = bh & 15;
    float inv0 = 1.f / lr0, inv1 = 1.f / lr1;
#pragma unroll
    for (int j = 0; j < 8; j++) {
        int d = 8 * j + 2 * tig;
        float* p0 = g_att + ((size_t)(b * TT + r0)) * CC + h * HD + d;
        float* p1 = g_att + ((size_t)(b * TT + r0 + 8)) * CC + h * HD + d;
        *(float2*)p0 = make_float2(oacc[j][0] * inv0, oacc[j][1] * inv0);
        *(float2*)p1 = make_float2(oacc[j][2] * inv1, oacc[j][3] * inv1);
    }
}

// ---------------------------------------------------------------------------

extern "C" void kernel_launch(void* const* d_in, const int* in_sizes, int n_in,
                              void* d_out, int out_size) {
    const float* x      = (const float*)d_in[0];
    const float* w_qkv  = (const float*)d_in[1];
    const float* w_proj = (const float*)d_in[2];
    const float* b_proj = (const float*)d_in[3];
    float* out = (float*)d_out;

    cudaFuncSetAttribute(tc_gemm<0>, cudaFuncAttributeMaxDynamicSharedMemorySize, GEMM_SMEM);
    cudaFuncSetAttribute(tc_gemm<1>, cudaFuncAttributeMaxDynamicSharedMemorySize, GEMM_SMEM);
    cudaFuncSetAttribute(attn_kernel, cudaFuncAttributeMaxDynamicSharedMemorySize, ATT_SMEM_BYTES);

    tc_gemm<0><<<dim3(N_QKV / 128, MROWS / 128), 256, GEMM_SMEM>>>(x, w_qkv, nullptr, nullptr);
    attn_kernel<<<dim3(TT / 128, BB * HH), 256, ATT_SMEM_BYTES>>>();
    tc_gemm<1><<<dim3(CC / 128, MROWS / 128), 256, GEMM_SMEM>>>(nullptr, w_proj, b_proj, out);
}

// round 6
// speedup vs baseline: 2.8250x; 1.1480x over previous
#include <cuda_runtime.h>
#include <cuda_bf16.h>
#include <math.h>
#include <stdint.h>

// Problem constants
#define BB 4
#define TT 2048
#define CC 1024
#define HH 16
#define HD 64
#define MROWS (BB * TT)          // 8192
#define N_QKV (3 * CC)           // 3072

// ---------------------------------------------------------------------------
// Global scratch (bf16 hi/lo pairs everywhere; allocation-free)
// ---------------------------------------------------------------------------
__device__ __nv_bfloat16 g_xh[MROWS * CC],  g_xl[MROWS * CC];
__device__ __nv_bfloat16 g_wqh[N_QKV * CC], g_wql[N_QKV * CC];
__device__ __nv_bfloat16 g_wph[CC * CC],    g_wpl[CC * CC];
__device__ __nv_bfloat16 g_qh[BB * HH * TT * HD], g_ql[BB * HH * TT * HD]; // [bh][t][d]
__device__ __nv_bfloat16 g_kh[BB * HH * TT * HD], g_kl[BB * HH * TT * HD]; // [bh][t][d]
__device__ __nv_bfloat16 g_vh[BB * HH * TT * HD], g_vl[BB * HH * TT * HD]; // [bh][d][t]
__device__ __nv_bfloat16 g_ah[MROWS * CC],  g_al[MROWS * CC];              // att out [B,T,C]

// ---------------------------------------------------------------------------
// Helpers
// ---------------------------------------------------------------------------
__device__ __forceinline__ uint32_t b2u(__nv_bfloat162 h) {
    return *reinterpret_cast<uint32_t*>(&h);
}
__device__ __forceinline__ uint32_t smem_u32(const void* p) {
    uint32_t a;
    asm("{ .reg .u64 t; cvta.to.shared.u64 t, %1; cvt.u32.u64 %0, t; }"
        : "=r"(a) : "l"(p));
    return a;
}
__device__ __forceinline__ void cpa16(uint32_t dst, const void* src) {
    asm volatile("cp.async.cg.shared.global [%0], [%1], 16;"
                 :: "r"(dst), "l"(src) : "memory");
}
#define CP_COMMIT() asm volatile("cp.async.commit_group;" ::: "memory")
#define CP_WAIT0()  asm volatile("cp.async.wait_group 0;" ::: "memory")
#define CP_WAIT1()  asm volatile("cp.async.wait_group 1;" ::: "memory")

__device__ __forceinline__ void mma16816(float* c, const uint32_t* a,
                                         uint32_t b0, uint32_t b1) {
    asm volatile(
        "mma.sync.aligned.m16n8k16.row.col.f32.bf16.bf16.f32 "
        "{%0,%1,%2,%3}, {%4,%5,%6,%7}, {%8,%9}, {%0,%1,%2,%3};"
        : "+f"(c[0]), "+f"(c[1]), "+f"(c[2]), "+f"(c[3])
        : "r"(a[0]), "r"(a[1]), "r"(a[2]), "r"(a[3]), "r"(b0), "r"(b1));
}

// ---------------------------------------------------------------------------
// Elementwise fp32 -> bf16 hi/lo split
// ---------------------------------------------------------------------------
__global__ void split_kernel(const float* __restrict__ src,
                             __nv_bfloat16* __restrict__ dh,
                             __nv_bfloat16* __restrict__ dl, int n4) {
    int i = blockIdx.x * blockDim.x + threadIdx.x;
    int stride = gridDim.x * blockDim.x;
    for (; i < n4; i += stride) {
        float4 v = ((const float4*)src)[i];
        __nv_bfloat162 h01 = __floats2bfloat162_rn(v.x, v.y);
        __nv_bfloat162 h23 = __floats2bfloat162_rn(v.z, v.w);
        __nv_bfloat162 l01 = __floats2bfloat162_rn(v.x - __bfloat162float(h01.x),
                                                   v.y - __bfloat162float(h01.y));
        __nv_bfloat162 l23 = __floats2bfloat162_rn(v.z - __bfloat162float(h23.x),
                                                   v.w - __bfloat162float(h23.y));
        ((uint2*)dh)[i] = make_uint2(b2u(h01), b2u(h23));
        ((uint2*)dl)[i] = make_uint2(b2u(l01), b2u(l23));
    }
}

// ---------------------------------------------------------------------------
// Split-bf16 NT GEMM, cp.async pipeline, 2 CTAs/SM.
// C[m,n] = sum_k A[m,k]*B[n,k]. 128x128 tile, K-chunk 32, 8 warps 4x2.
// EPI=0: write Q/K/V split bf16 (V transposed). EPI=1: out = C + bias (fp32).
// ---------------------------------------------------------------------------
#define APAD_B 80                          // bytes per smem row (32 bf16 + pad)
#define TILE_B (128 * APAD_B)              // 10240
#define BUF_B  (4 * TILE_B)                // AH, AL, BH, BL = 40960
#define GEMM_SMEM (2 * BUF_B)              // 81920
#define NCHUNK (CC / 32)                   // 32

template <int EPI>
__global__ __launch_bounds__(256, 2) void tc_gemm(
    const __nv_bfloat16* __restrict__ AH, const __nv_bfloat16* __restrict__ AL,
    const __nv_bfloat16* __restrict__ BH, const __nv_bfloat16* __restrict__ BL,
    const float* __restrict__ bias, float* __restrict__ out) {
    extern __shared__ char smc[];
    const uint32_t smb = smem_u32(smc);
    const int tid = threadIdx.x;
    const int m0 = blockIdx.y * 128;
    const int n0 = blockIdx.x * 128;
    const int wid = tid >> 5;
    const int lane = tid & 31;
    const int gid = lane >> 2;
    const int tig = lane & 3;
    const int wm = wid & 3;
    const int wn = wid >> 2;

    float acc[2][8][4];
#pragma unroll
    for (int i = 0; i < 2; i++)
#pragma unroll
        for (int j = 0; j < 8; j++)
#pragma unroll
            for (int q = 0; q < 4; q++) acc[i][j][q] = 0.f;

    // cp.async one chunk (4 tiles x 512 x 16B) into buffer bufi
    auto copyc = [&](int kk, int bufi) {
        uint32_t bbase = smb + bufi * BUF_B;
#pragma unroll
        for (int l = 0; l < 8; l++) {
            const int tile = l >> 1;                 // compile-time per unroll
            int e2 = (l & 1) * 256 + tid;            // 0..511
            int r = e2 >> 2;
            int q = e2 & 3;
            const __nv_bfloat16* src =
                (tile == 0) ? AH : (tile == 1) ? AL : (tile == 2) ? BH : BL;
            int row = (tile < 2 ? m0 : n0) + r;
            cpa16(bbase + tile * TILE_B + r * APAD_B + q * 16,
                  src + (size_t)row * CC + kk + q * 8);
        }
    };

    auto compute = [&](const char* buf) {
#pragma unroll
        for (int ks = 0; ks < 2; ks++) {
            uint32_t ah[2][4], al[2][4];
#pragma unroll
            for (int i = 0; i < 2; i++) {
                int row = wm * 32 + i * 16 + gid;
                uint32_t o = (uint32_t)(row * APAD_B + ks * 32 + tig * 4);
                ah[i][0] = *(const uint32_t*)(buf + o);
                ah[i][1] = *(const uint32_t*)(buf + o + 8 * APAD_B);
                ah[i][2] = *(const uint32_t*)(buf + o + 16);
                ah[i][3] = *(const uint32_t*)(buf + o + 8 * APAD_B + 16);
                al[i][0] = *(const uint32_t*)(buf + TILE_B + o);
                al[i][1] = *(const uint32_t*)(buf + TILE_B + o + 8 * APAD_B);
                al[i][2] = *(const uint32_t*)(buf + TILE_B + o + 16);
                al[i][3] = *(const uint32_t*)(buf + TILE_B + o + 8 * APAD_B + 16);
            }
#pragma unroll
            for (int j = 0; j < 8; j++) {
                int n = wn * 64 + j * 8 + gid;
                uint32_t o = (uint32_t)(n * APAD_B + ks * 32 + tig * 4);
                uint32_t bh0 = *(const uint32_t*)(buf + 2 * TILE_B + o);
                uint32_t bh1 = *(const uint32_t*)(buf + 2 * TILE_B + o + 16);
                uint32_t bl0 = *(const uint32_t*)(buf + 3 * TILE_B + o);
                uint32_t bl1 = *(const uint32_t*)(buf + 3 * TILE_B + o + 16);
#pragma unroll
                for (int i = 0; i < 2; i++) {
                    mma16816(acc[i][j], ah[i], bh0, bh1);
                    mma16816(acc[i][j], ah[i], bl0, bl1);
                    mma16816(acc[i][j], al[i], bh0, bh1);
                }
            }
        }
    };

    copyc(0, 0);
    CP_COMMIT();
    for (int c = 0; c < NCHUNK; c++) {
        if (c + 1 < NCHUNK) {
            copyc((c + 1) * 32, (c + 1) & 1);
            CP_COMMIT();
            CP_WAIT1();
        } else {
            CP_WAIT0();
        }
        __syncthreads();
        compute(smc + (size_t)(c & 1) * BUF_B);
        __syncthreads();
    }

    // ---- epilogue: fragments -> smem staging
    float* Ds = (float*)smc;               // 128 x 132 f32 = 67584 <= 81920
#pragma unroll
    for (int i = 0; i < 2; i++) {
        int rr = wm * 32 + i * 16 + gid;
#pragma unroll
        for (int j = 0; j < 8; j++) {
            int cc = wn * 64 + j * 8 + tig * 2;
            *(float2*)&Ds[rr * 132 + cc]       = make_float2(acc[i][j][0], acc[i][j][1]);
            *(float2*)&Ds[(rr + 8) * 132 + cc] = make_float2(acc[i][j][2], acc[i][j][3]);
        }
    }
    __syncthreads();

    if (EPI == 1) {
#pragma unroll 4
        for (int ll = 0; ll < 64; ll++) {
            int flat = ll * 256 + tid;
            int n = flat & 127;
            int m = flat >> 7;
            out[(size_t)(m0 + m) * CC + n0 + n] = Ds[m * 132 + n] + bias[n0 + n];
        }
    } else {
        // two 64-wide segments; each wholly one of q/k/v (192 % 64 == 0)
#pragma unroll
        for (int seg = 0; seg < 2; seg++) {
            int gn0 = n0 + seg * 64;
            int h = gn0 / 192;
            int part = (gn0 % 192) >> 6;
            if (part < 2) {
                __nv_bfloat16* dh = (part == 0) ? g_qh : g_kh;
                __nv_bfloat16* dl = (part == 0) ? g_ql : g_kl;
#pragma unroll
                for (int it = 0; it < 16; it++) {
                    int m = it * 8 + (tid >> 5);
                    int d2 = (tid & 31) * 2;
                    float v0 = Ds[m * 132 + seg * 64 + d2];
                    float v1 = Ds[m * 132 + seg * 64 + d2 + 1];
                    __nv_bfloat162 hp = __floats2bfloat162_rn(v0, v1);
                    __nv_bfloat162 lp = __floats2bfloat162_rn(
                        v0 - __bfloat162float(hp.x), v1 - __bfloat162float(hp.y));
                    int gm = m0 + m; int b = gm >> 11; int t = gm & 2047;
                    size_t idx = (((size_t)(b * HH + h)) * TT + t) * HD + d2;
                    *(__nv_bfloat162*)(dh + idx) = hp;
                    *(__nv_bfloat162*)(dl + idx) = lp;
                }
            } else {                        // V: transposed [bh][d][t]
#pragma unroll
                for (int it = 0; it < 16; it++) {
                    int flat = it * 256 + tid;     // 0..4095
                    int d = flat >> 6;             // 0..63
                    int tp = (flat & 63) * 2;      // 0..126 (pair along t)
                    float v0 = Ds[tp * 132 + seg * 64 + d];
                    float v1 = Ds[(tp + 1) * 132 + seg * 64 + d];
                    __nv_bfloat162 hp = __floats2bfloat162_rn(v0, v1);
                    __nv_bfloat162 lp = __floats2bfloat162_rn(
                        v0 - __bfloat162float(hp.x), v1 - __bfloat162float(hp.y));
                    int gm = m0 + tp; int b = gm >> 11; int t = gm & 2047;
                    size_t idx = (((size_t)(b * HH + h)) * HD + d) * TT + t;
                    *(__nv_bfloat162*)(g_vh + idx) = hp;
                    *(__nv_bfloat162*)(g_vl + idx) = lp;
                }
            }
        }
    }
}

// ---------------------------------------------------------------------------
// Flash attention, split-bf16 mma. BM=128 (8 warps x 16 rows), BN=64.
// All operands pre-split bf16 in global; cp.async double-buffered K/V tiles.
// Smem row stride 144B -> conflict-free fragment loads.
// ---------------------------------------------------------------------------
#define AT_ROW 144
#define AT_TILE (64 * AT_ROW)              // 9216
#define AT_BUF (4 * AT_TILE)               // 36864
#define ATT_SMEM_BYTES (2 * AT_BUF)        // 73728

__global__ __launch_bounds__(256) void attn_kernel() {
    extern __shared__ char smc[];
    const uint32_t smb = smem_u32(smc);
    const int tid = threadIdx.x;
    const int bh = blockIdx.y;
    const int q0 = blockIdx.x * 128;
    const int wid = tid >> 5;
    const int lane = tid & 31;
    const int gid = lane >> 2;
    const int tig = lane & 3;
    const int r0 = q0 + wid * 16 + gid;

    const __nv_bfloat16* Qh = g_qh + (size_t)bh * TT * HD;
    const __nv_bfloat16* Ql = g_ql + (size_t)bh * TT * HD;
    const __nv_bfloat16* Kh = g_kh + (size_t)bh * TT * HD;
    const __nv_bfloat16* Kl = g_kl + (size_t)bh * TT * HD;
    const __nv_bfloat16* Vh = g_vh + (size_t)bh * HD * TT;
    const __nv_bfloat16* Vl = g_vl + (size_t)bh * HD * TT;

    // ---- Q fragments (pre-split), direct ldg
    uint32_t qh[4][4], ql[4][4];
#pragma unroll
    for (int ks = 0; ks < 4; ks++)
#pragma unroll
        for (int hv = 0; hv < 2; hv++)
#pragma unroll
            for (int rr = 0; rr < 2; rr++) {
                size_t o = (size_t)(r0 + rr * 8) * HD + ks * 16 + hv * 8 + tig * 2;
                qh[ks][hv * 2 + rr] = *(const uint32_t*)(Qh + o);
                ql[ks][hv * 2 + rr] = *(const uint32_t*)(Ql + o);
            }

    float oacc[8][4];
#pragma unroll
    for (int j = 0; j < 8; j++)
#pragma unroll
        for (int q = 0; q < 4; q++) oacc[j][q] = 0.f;
    float mr0 = -1e30f, mr1 = -1e30f, lr0 = 0.f, lr1 = 0.f;

    auto copyc = [&](int c, int bufi) {
        const int k0 = c * 64;
        uint32_t bbase = smb + bufi * AT_BUF;
#pragma unroll
        for (int l = 0; l < 8; l++) {
            const int tile = l >> 1;
            int e2 = (l & 1) * 256 + tid;       // 0..511
            int r = e2 >> 3;                    // 0..63
            int q = e2 & 7;                     // 0..7
            const __nv_bfloat16* src;
            if (tile == 0)      src = Kh + (size_t)(k0 + r) * HD + q * 8;
            else if (tile == 1) src = Kl + (size_t)(k0 + r) * HD + q * 8;
            else if (tile == 2) src = Vh + (size_t)r * TT + k0 + q * 8;
            else                src = Vl + (size_t)r * TT + k0 + q * 8;
            cpa16(bbase + tile * AT_TILE + r * AT_ROW + q * 16, src);
        }
    };

    const int jmax = (q0 >> 6) + 2;
    copyc(0, 0);
    CP_COMMIT();
    for (int c = 0; c < jmax; c++) {
        if (c + 1 < jmax) {
            copyc(c + 1, (c + 1) & 1);
            CP_COMMIT();
            CP_WAIT1();
        } else {
            CP_WAIT0();
        }
        __syncthreads();
        const char* KhT = smc + (size_t)(c & 1) * AT_BUF;
        const char* KlT = KhT + AT_TILE;
        const char* VhT = KhT + 2 * AT_TILE;
        const char* VlT = KhT + 3 * AT_TILE;

        // ---- S = Q K^T (qh*kh + qh*kl + ql*kh)
        float s[8][4];
#pragma unroll
        for (int j = 0; j < 8; j++)
#pragma unroll
            for (int q = 0; q < 4; q++) s[j][q] = 0.f;
#pragma unroll
        for (int ks = 0; ks < 4; ks++) {
#pragma unroll
            for (int j = 0; j < 8; j++) {
                uint32_t o = (uint32_t)((8 * j + gid) * AT_ROW + ks * 32 + tig * 4);
                uint32_t bh0 = *(const uint32_t*)(KhT + o);
                uint32_t bh1 = *(const uint32_t*)(KhT + o + 16);
                uint32_t bl0 = *(const uint32_t*)(KlT + o);
                uint32_t bl1 = *(const uint32_t*)(KlT + o + 16);
                mma16816(s[j], qh[ks], bh0, bh1);
                mma16816(s[j], qh[ks], bl0, bl1);
                mma16816(s[j], ql[ks], bh0, bh1);
            }
        }

        const int k0 = c * 64;
#pragma unroll
        for (int j = 0; j < 8; j++)
#pragma unroll
            for (int q = 0; q < 4; q++) s[j][q] *= 0.125f;
        if (c >= jmax - 2) {
#pragma unroll
            for (int j = 0; j < 8; j++) {
                int col = k0 + 8 * j + 2 * tig;
                if (col > r0)          s[j][0] = -1e30f;
                if (col + 1 > r0)      s[j][1] = -1e30f;
                if (col > r0 + 8)      s[j][2] = -1e30f;
                if (col + 1 > r0 + 8)  s[j][3] = -1e30f;
            }
        }

        // ---- online softmax
        float pm0 = -1e30f, pm1 = -1e30f;
#pragma unroll
        for (int j = 0; j < 8; j++) {
            pm0 = fmaxf(pm0, fmaxf(s[j][0], s[j][1]));
            pm1 = fmaxf(pm1, fmaxf(s[j][2], s[j][3]));
        }
        pm0 = fmaxf(pm0, __shfl_xor_sync(0xffffffffu, pm0, 1));
        pm0 = fmaxf(pm0, __shfl_xor_sync(0xffffffffu, pm0, 2));
        pm1 = fmaxf(pm1, __shfl_xor_sync(0xffffffffu, pm1, 1));
        pm1 = fmaxf(pm1, __shfl_xor_sync(0xffffffffu, pm1, 2));
        float mn0 = fmaxf(mr0, pm0), mn1 = fmaxf(mr1, pm1);
        float a0 = __expf(mr0 - mn0), a1 = __expf(mr1 - mn1);
        float sum0 = 0.f, sum1 = 0.f;
#pragma unroll
        for (int j = 0; j < 8; j++) {
            s[j][0] = __expf(s[j][0] - mn0);
            s[j][1] = __expf(s[j][1] - mn0);
            s[j][2] = __expf(s[j][2] - mn1);
            s[j][3] = __expf(s[j][3] - mn1);
            sum0 += s[j][0] + s[j][1];
            sum1 += s[j][2] + s[j][3];
        }
        sum0 += __shfl_xor_sync(0xffffffffu, sum0, 1);
        sum0 += __shfl_xor_sync(0xffffffffu, sum0, 2);
        sum1 += __shfl_xor_sync(0xffffffffu, sum1, 1);
        sum1 += __shfl_xor_sync(0xffffffffu, sum1, 2);
        lr0 = lr0 * a0 + sum0;
        lr1 = lr1 * a1 + sum1;
        mr0 = mn0; mr1 = mn1;
#pragma unroll
        for (int j = 0; j < 8; j++) {
            oacc[j][0] *= a0; oacc[j][1] *= a0;
            oacc[j][2] *= a1; oacc[j][3] *= a1;
        }

        // ---- pack P fragments (bf16 hi/lo) from S accumulators
        uint32_t pah[4][4], pal[4][4];
#pragma unroll
        for (int ks = 0; ks < 4; ks++) {
            int j0 = 2 * ks, j1 = 2 * ks + 1;
#pragma unroll
            for (int part = 0; part < 4; part++) {
                int jj = (part < 2) ? j0 : j1;
                int qa = (part & 1) * 2;
                float x = s[jj][qa], y = s[jj][qa + 1];
                __nv_bfloat162 hp = __floats2bfloat162_rn(x, y);
                __nv_bfloat162 lp = __floats2bfloat162_rn(
                    x - __bfloat162float(hp.x), y - __bfloat162float(hp.y));
                pah[ks][part] = b2u(hp);
                pal[ks][part] = b2u(lp);
            }
        }

        // ---- O += P V (ph*vh + ph*vl + pl*vh)
#pragma unroll
        for (int ks = 0; ks < 4; ks++) {
#pragma unroll
            for (int j = 0; j < 8; j++) {
                uint32_t o = (uint32_t)((8 * j + gid) * AT_ROW + ks * 32 + tig * 4);
                uint32_t vh0 = *(const uint32_t*)(VhT + o);
                uint32_t vh1 = *(const uint32_t*)(VhT + o + 16);
                uint32_t vl0 = *(const uint32_t*)(VlT + o);
                uint32_t vl1 = *(const uint32_t*)(VlT + o + 16);
                mma16816(oacc[j], pah[ks], vh0, vh1);
                mma16816(oacc[j], pah[ks], vl0, vl1);
                mma16816(oacc[j], pal[ks], vh0, vh1);
            }
        }
        __syncthreads();
    }

    // ---- epilogue: normalize, split bf16, write g_ah/g_al [B,T,C]
    const int b = bh >> 4;
    const int h = bh & 15;
    float inv0 = 1.f / lr0, inv1 = 1.f / lr1;
#pragma unroll
    for (int j = 0; j < 8; j++) {
        int d = 8 * j + 2 * tig;
        size_t o0 = ((size_t)(b * TT + r0)) * CC + h * HD + d;
        size_t o1 = ((size_t)(b * TT + r0 + 8)) * CC + h * HD + d;
        float x0 = oacc[j][0] * inv0, y0 = oacc[j][1] * inv0;
        float x1 = oacc[j][2] * inv1, y1 = oacc[j][3] * inv1;
        __nv_bfloat162 h0 = __floats2bfloat162_rn(x0, y0);
        __nv_bfloat162 l0 = __floats2bfloat162_rn(x0 - __bfloat162float(h0.x),
                                                  y0 - __bfloat162float(h0.y));
        __nv_bfloat162 h1 = __floats2bfloat162_rn(x1, y1);
        __nv_bfloat162 l1 = __floats2bfloat162_rn(x1 - __bfloat162float(h1.x),
                                                  y1 - __bfloat162float(h1.y));
        *(__nv_bfloat162*)(g_ah + o0) = h0;
        *(__nv_bfloat162*)(g_al + o0) = l0;
        *(__nv_bfloat162*)(g_ah + o1) = h1;
        *(__nv_bfloat162*)(g_al + o1) = l1;
    }
}

// ---------------------------------------------------------------------------

extern "C" void kernel_launch(void* const* d_in, const int* in_sizes, int n_in,
                              void* d_out, int out_size) {
    const float* x      = (const float*)d_in[0];
    const float* w_qkv  = (const float*)d_in[1];
    const float* w_proj = (const float*)d_in[2];
    const float* b_proj = (const float*)d_in[3];
    float* out = (float*)d_out;

    __nv_bfloat16 *xh, *xl, *wqh, *wql, *wph, *wpl, *ah, *al;
    cudaGetSymbolAddress((void**)&xh,  g_xh);
    cudaGetSymbolAddress((void**)&xl,  g_xl);
    cudaGetSymbolAddress((void**)&wqh, g_wqh);
    cudaGetSymbolAddress((void**)&wql, g_wql);
    cudaGetSymbolAddress((void**)&wph, g_wph);
    cudaGetSymbolAddress((void**)&wpl, g_wpl);
    cudaGetSymbolAddress((void**)&ah,  g_ah);
    cudaGetSymbolAddress((void**)&al,  g_al);

    cudaFuncSetAttribute(tc_gemm<0>, cudaFuncAttributeMaxDynamicSharedMemorySize, GEMM_SMEM);
    cudaFuncSetAttribute(tc_gemm<1>, cudaFuncAttributeMaxDynamicSharedMemorySize, GEMM_SMEM);
    cudaFuncSetAttribute(attn_kernel, cudaFuncAttributeMaxDynamicSharedMemorySize, ATT_SMEM_BYTES);

    split_kernel<<<2048, 256>>>(x, xh, xl, MROWS * CC / 4);
    split_kernel<<<2048, 256>>>(w_qkv, wqh, wql, N_QKV * CC / 4);
    split_kernel<<<1024, 256>>>(w_proj, wph, wpl, CC * CC / 4);

    tc_gemm<0><<<dim3(N_QKV / 128, MROWS / 128), 256, GEMM_SMEM>>>(
        xh, xl, wqh, wql, nullptr, nullptr);
    attn_kernel<<<dim3(TT / 128, BB * HH), 256, ATT_SMEM_BYTES>>>();
    tc_gemm<1><<<dim3(CC / 128, MROWS / 128), 256, GEMM_SMEM>>>(
        ah, al, wph, wpl, b_proj, out);
}

// round 7
// speedup vs baseline: 2.8868x; 1.0219x over previous
#include <cuda_runtime.h>
#include <cuda_bf16.h>
#include <math.h>
#include <stdint.h>

// Problem constants
#define BB 4
#define TT 2048
#define CC 1024
#define HH 16
#define HD 64
#define MROWS (BB * TT)          // 8192
#define N_QKV (3 * CC)           // 3072

// ---------------------------------------------------------------------------
// Global scratch (bf16 hi/lo pairs everywhere; allocation-free)
// ---------------------------------------------------------------------------
__device__ __nv_bfloat16 g_xh[MROWS * CC],  g_xl[MROWS * CC];
__device__ __nv_bfloat16 g_wqh[N_QKV * CC], g_wql[N_QKV * CC];
__device__ __nv_bfloat16 g_wph[CC * CC],    g_wpl[CC * CC];
__device__ __nv_bfloat16 g_qh[BB * HH * TT * HD], g_ql[BB * HH * TT * HD]; // [bh][t][d]
__device__ __nv_bfloat16 g_kh[BB * HH * TT * HD], g_kl[BB * HH * TT * HD]; // [bh][t][d]
__device__ __nv_bfloat16 g_vh[BB * HH * TT * HD], g_vl[BB * HH * TT * HD]; // [bh][d][t]
__device__ __nv_bfloat16 g_ah[MROWS * CC],  g_al[MROWS * CC];              // att out [B,T,C]

// ---------------------------------------------------------------------------
// Helpers
// ---------------------------------------------------------------------------
__device__ __forceinline__ uint32_t b2u(__nv_bfloat162 h) {
    return *reinterpret_cast<uint32_t*>(&h);
}
__device__ __forceinline__ uint32_t smem_u32(const void* p) {
    uint32_t a;
    asm("{ .reg .u64 t; cvta.to.shared.u64 t, %1; cvt.u32.u64 %0, t; }"
        : "=r"(a) : "l"(p));
    return a;
}
__device__ __forceinline__ void cpa16(uint32_t dst, const void* src) {
    asm volatile("cp.async.cg.shared.global [%0], [%1], 16;"
                 :: "r"(dst), "l"(src) : "memory");
}
#define CP_COMMIT() asm volatile("cp.async.commit_group;" ::: "memory")
#define CP_WAIT0()  asm volatile("cp.async.wait_group 0;" ::: "memory")
#define CP_WAIT1()  asm volatile("cp.async.wait_group 1;" ::: "memory")

#define LDSM4(r, addr) \
    asm volatile("ldmatrix.sync.aligned.m8n8.x4.shared.b16 {%0,%1,%2,%3}, [%4];" \
        : "=r"((r)[0]), "=r"((r)[1]), "=r"((r)[2]), "=r"((r)[3]) : "r"(addr))

__device__ __forceinline__ void mma16816(float* c, const uint32_t* a,
                                         uint32_t b0, uint32_t b1) {
    asm volatile(
        "mma.sync.aligned.m16n8k16.row.col.f32.bf16.bf16.f32 "
        "{%0,%1,%2,%3}, {%4,%5,%6,%7}, {%8,%9}, {%0,%1,%2,%3};"
        : "+f"(c[0]), "+f"(c[1]), "+f"(c[2]), "+f"(c[3])
        : "r"(a[0]), "r"(a[1]), "r"(a[2]), "r"(a[3]), "r"(b0), "r"(b1));
}

// ---------------------------------------------------------------------------
// Elementwise fp32 -> bf16 hi/lo split
// ---------------------------------------------------------------------------
__global__ void split_kernel(const float* __restrict__ src,
                             __nv_bfloat16* __restrict__ dh,
                             __nv_bfloat16* __restrict__ dl, int n4) {
    int i = blockIdx.x * blockDim.x + threadIdx.x;
    int stride = gridDim.x * blockDim.x;
    for (; i < n4; i += stride) {
        float4 v = ((const float4*)src)[i];
        __nv_bfloat162 h01 = __floats2bfloat162_rn(v.x, v.y);
        __nv_bfloat162 h23 = __floats2bfloat162_rn(v.z, v.w);
        __nv_bfloat162 l01 = __floats2bfloat162_rn(v.x - __bfloat162float(h01.x),
                                                   v.y - __bfloat162float(h01.y));
        __nv_bfloat162 l23 = __floats2bfloat162_rn(v.z - __bfloat162float(h23.x),
                                                   v.w - __bfloat162float(h23.y));
        ((uint2*)dh)[i] = make_uint2(b2u(h01), b2u(h23));
        ((uint2*)dl)[i] = make_uint2(b2u(l01), b2u(l23));
    }
}

// ---------------------------------------------------------------------------
// Split-bf16 NT GEMM, cp.async pipeline, ldmatrix fragments, 2 CTAs/SM.
// C[m,n] = sum_k A[m,k]*B[n,k]. 128x128 tile, K-chunk 32, 8 warps 4x2.
// EPI=0: write Q/K/V split bf16 (V transposed). EPI=1: out = C + bias (fp32).
// ---------------------------------------------------------------------------
#define APAD_B 80                          // bytes per smem row (16B-mult, LDSM conflict-free)
#define TILE_B (128 * APAD_B)              // 10240
#define BUF_B  (4 * TILE_B)                // AH, AL, BH, BL = 40960
#define GEMM_SMEM (2 * BUF_B)              // 81920
#define NCHUNK (CC / 32)                   // 32

template <int EPI>
__global__ __launch_bounds__(256, 2) void tc_gemm(
    const __nv_bfloat16* __restrict__ AH, const __nv_bfloat16* __restrict__ AL,
    const __nv_bfloat16* __restrict__ BH, const __nv_bfloat16* __restrict__ BL,
    const float* __restrict__ bias, float* __restrict__ out) {
    extern __shared__ char smc[];
    const uint32_t smb = smem_u32(smc);
    const int tid = threadIdx.x;
    const int m0 = blockIdx.y * 128;
    const int n0 = blockIdx.x * 128;
    const int wid = tid >> 5;
    const int lane = tid & 31;
    const int gid = lane >> 2;
    const int tig = lane & 3;
    const int wm = wid & 3;
    const int wn = wid >> 2;

    // ldmatrix.x4 per-lane offsets
    // A: m0=(r0-7,k0-7) m1=(r8-15,k0-7) m2=(r0-7,k8-15) m3=(r8-15,k8-15)
    const uint32_t laneA = (uint32_t)(((lane & 7) + ((lane >> 3) & 1) * 8) * APAD_B
                                      + (lane >> 4) * 16);
    // B: m0=(n0-7,k0-7) m1=(n0-7,k8-15) m2=(n8-15,k0-7) m3=(n8-15,k8-15)
    const uint32_t laneB = (uint32_t)(((lane & 7) + ((lane >> 4) & 1) * 8) * APAD_B
                                      + ((lane >> 3) & 1) * 16);

    float acc[2][8][4];
#pragma unroll
    for (int i = 0; i < 2; i++)
#pragma unroll
        for (int j = 0; j < 8; j++)
#pragma unroll
            for (int q = 0; q < 4; q++) acc[i][j][q] = 0.f;

    // cp.async one chunk (4 tiles x 512 x 16B) into buffer bufi
    auto copyc = [&](int kk, int bufi) {
        uint32_t bbase = smb + bufi * BUF_B;
#pragma unroll
        for (int l = 0; l < 8; l++) {
            const int tile = l >> 1;                 // compile-time per unroll
            int e2 = (l & 1) * 256 + tid;            // 0..511
            int r = e2 >> 2;
            int q = e2 & 3;
            const __nv_bfloat16* src =
                (tile == 0) ? AH : (tile == 1) ? AL : (tile == 2) ? BH : BL;
            int row = (tile < 2 ? m0 : n0) + r;
            cpa16(bbase + tile * TILE_B + r * APAD_B + q * 16,
                  src + (size_t)row * CC + kk + q * 8);
        }
    };

    auto compute = [&](uint32_t bufu) {
#pragma unroll
        for (int ks = 0; ks < 2; ks++) {
            uint32_t ah[2][4], al[2][4];
#pragma unroll
            for (int i = 0; i < 2; i++) {
                uint32_t aaddr = bufu + laneA + (wm * 32 + i * 16) * APAD_B + ks * 32;
                LDSM4(ah[i], aaddr);
                LDSM4(al[i], aaddr + TILE_B);
            }
#pragma unroll
            for (int jp = 0; jp < 4; jp++) {
                uint32_t baddr = bufu + 2 * TILE_B + laneB
                               + (wn * 64 + jp * 16) * APAD_B + ks * 32;
                uint32_t rh[4], rl[4];
                LDSM4(rh, baddr);
                LDSM4(rl, baddr + TILE_B);
#pragma unroll
                for (int t = 0; t < 2; t++) {
                    int j = 2 * jp + t;
#pragma unroll
                    for (int i = 0; i < 2; i++) {
                        mma16816(acc[i][j], ah[i], rh[2 * t], rh[2 * t + 1]);
                        mma16816(acc[i][j], ah[i], rl[2 * t], rl[2 * t + 1]);
                        mma16816(acc[i][j], al[i], rh[2 * t], rh[2 * t + 1]);
                    }
                }
            }
        }
    };

    copyc(0, 0);
    CP_COMMIT();
    for (int c = 0; c < NCHUNK; c++) {
        if (c + 1 < NCHUNK) {
            copyc((c + 1) * 32, (c + 1) & 1);
            CP_COMMIT();
            CP_WAIT1();
        } else {
            CP_WAIT0();
        }
        __syncthreads();
        compute(smb + (uint32_t)(c & 1) * BUF_B);
        __syncthreads();
    }

    // ---- epilogue: fragments -> smem staging
    float* Ds = (float*)smc;               // 128 x 132 f32 = 67584 <= 81920
#pragma unroll
    for (int i = 0; i < 2; i++) {
        int rr = wm * 32 + i * 16 + gid;
#pragma unroll
        for (int j = 0; j < 8; j++) {
            int cc = wn * 64 + j * 8 + tig * 2;
            *(float2*)&Ds[rr * 132 + cc]       = make_float2(acc[i][j][0], acc[i][j][1]);
            *(float2*)&Ds[(rr + 8) * 132 + cc] = make_float2(acc[i][j][2], acc[i][j][3]);
        }
    }
    __syncthreads();

    if (EPI == 1) {
#pragma unroll 4
        for (int ll = 0; ll < 64; ll++) {
            int flat = ll * 256 + tid;
            int n = flat & 127;
            int m = flat >> 7;
            out[(size_t)(m0 + m) * CC + n0 + n] = Ds[m * 132 + n] + bias[n0 + n];
        }
    } else {
        // two 64-wide segments; each wholly one of q/k/v (192 % 64 == 0)
#pragma unroll
        for (int seg = 0; seg < 2; seg++) {
            int gn0 = n0 + seg * 64;
            int h = gn0 / 192;
            int part = (gn0 % 192) >> 6;
            if (part < 2) {
                __nv_bfloat16* dh = (part == 0) ? g_qh : g_kh;
                __nv_bfloat16* dl = (part == 0) ? g_ql : g_kl;
#pragma unroll
                for (int it = 0; it < 16; it++) {
                    int m = it * 8 + (tid >> 5);
                    int d2 = (tid & 31) * 2;
                    float v0 = Ds[m * 132 + seg * 64 + d2];
                    float v1 = Ds[m * 132 + seg * 64 + d2 + 1];
                    __nv_bfloat162 hp = __floats2bfloat162_rn(v0, v1);
                    __nv_bfloat162 lp = __floats2bfloat162_rn(
                        v0 - __bfloat162float(hp.x), v1 - __bfloat162float(hp.y));
                    int gm = m0 + m; int b = gm >> 11; int t = gm & 2047;
                    size_t idx = (((size_t)(b * HH + h)) * TT + t) * HD + d2;
                    *(__nv_bfloat162*)(dh + idx) = hp;
                    *(__nv_bfloat162*)(dl + idx) = lp;
                }
            } else {                        // V: transposed [bh][d][t]
#pragma unroll
                for (int it = 0; it < 16; it++) {
                    int flat = it * 256 + tid;     // 0..4095
                    int d = flat >> 6;             // 0..63
                    int tp = (flat & 63) * 2;      // 0..126 (pair along t)
                    float v0 = Ds[tp * 132 + seg * 64 + d];
                    float v1 = Ds[(tp + 1) * 132 + seg * 64 + d];
                    __nv_bfloat162 hp = __floats2bfloat162_rn(v0, v1);
                    __nv_bfloat162 lp = __floats2bfloat162_rn(
                        v0 - __bfloat162float(hp.x), v1 - __bfloat162float(hp.y));
                    int gm = m0 + tp; int b = gm >> 11; int t = gm & 2047;
                    size_t idx = (((size_t)(b * HH + h)) * HD + d) * TT + t;
                    *(__nv_bfloat162*)(g_vh + idx) = hp;
                    *(__nv_bfloat162*)(g_vl + idx) = lp;
                }
            }
        }
    }
}

// ---------------------------------------------------------------------------
// Flash attention, split-bf16 mma + ldmatrix. BM=128 (8 warps x 16 rows), BN=64.
// All operands pre-split bf16 in global; cp.async double-buffered K/V tiles.
// Smem row stride 144B (16B-mult, LDSM conflict-free).
// ---------------------------------------------------------------------------
#define AT_ROW 144
#define AT_TILE (64 * AT_ROW)              // 9216
#define AT_BUF (4 * AT_TILE)               // 36864
#define ATT_SMEM_BYTES (2 * AT_BUF)        // 73728

__global__ __launch_bounds__(256) void attn_kernel() {
    extern __shared__ char smc[];
    const uint32_t smb = smem_u32(smc);
    const int tid = threadIdx.x;
    const int bh = blockIdx.y;
    const int q0 = blockIdx.x * 128;
    const int wid = tid >> 5;
    const int lane = tid & 31;
    const int gid = lane >> 2;
    const int tig = lane & 3;
    const int r0 = q0 + wid * 16 + gid;

    const __nv_bfloat16* Qh = g_qh + (size_t)bh * TT * HD;
    const __nv_bfloat16* Ql = g_ql + (size_t)bh * TT * HD;
    const __nv_bfloat16* Kh = g_kh + (size_t)bh * TT * HD;
    const __nv_bfloat16* Kl = g_kl + (size_t)bh * TT * HD;
    const __nv_bfloat16* Vh = g_vh + (size_t)bh * HD * TT;
    const __nv_bfloat16* Vl = g_vl + (size_t)bh * HD * TT;

    // B-operand ldmatrix lane offset (stride AT_ROW)
    const uint32_t laneB = (uint32_t)(((lane & 7) + ((lane >> 4) & 1) * 8) * AT_ROW
                                      + ((lane >> 3) & 1) * 16);

    // ---- Q fragments (pre-split), direct ldg
    uint32_t qh[4][4], ql[4][4];
#pragma unroll
    for (int ks = 0; ks < 4; ks++)
#pragma unroll
        for (int hv = 0; hv < 2; hv++)
#pragma unroll
            for (int rr = 0; rr < 2; rr++) {
                size_t o = (size_t)(r0 + rr * 8) * HD + ks * 16 + hv * 8 + tig * 2;
                qh[ks][hv * 2 + rr] = *(const uint32_t*)(Qh + o);
                ql[ks][hv * 2 + rr] = *(const uint32_t*)(Ql + o);
            }

    float oacc[8][4];
#pragma unroll
    for (int j = 0; j < 8; j++)
#pragma unroll
        for (int q = 0; q < 4; q++) oacc[j][q] = 0.f;
    float mr0 = -1e30f, mr1 = -1e30f, lr0 = 0.f, lr1 = 0.f;

    auto copyc = [&](int c, int bufi) {
        const int k0 = c * 64;
        uint32_t bbase = smb + bufi * AT_BUF;
#pragma unroll
        for (int l = 0; l < 8; l++) {
            const int tile = l >> 1;
            int e2 = (l & 1) * 256 + tid;       // 0..511
            int r = e2 >> 3;                    // 0..63
            int q = e2 & 7;                     // 0..7
            const __nv_bfloat16* src;
            if (tile == 0)      src = Kh + (size_t)(k0 + r) * HD + q * 8;
            else if (tile == 1) src = Kl + (size_t)(k0 + r) * HD + q * 8;
            else if (tile == 2) src = Vh + (size_t)r * TT + k0 + q * 8;
            else                src = Vl + (size_t)r * TT + k0 + q * 8;
            cpa16(bbase + tile * AT_TILE + r * AT_ROW + q * 16, src);
        }
    };

    const int jmax = (q0 >> 6) + 2;
    copyc(0, 0);
    CP_COMMIT();
    for (int c = 0; c < jmax; c++) {
        if (c + 1 < jmax) {
            copyc(c + 1, (c + 1) & 1);
            CP_COMMIT();
            CP_WAIT1();
        } else {
            CP_WAIT0();
        }
        __syncthreads();
        const uint32_t KT = smb + (uint32_t)(c & 1) * AT_BUF;
        const uint32_t VT = KT + 2 * AT_TILE;

        // ---- S = Q K^T (qh*kh + qh*kl + ql*kh)
        float s[8][4];
#pragma unroll
        for (int j = 0; j < 8; j++)
#pragma unroll
            for (int q = 0; q < 4; q++) s[j][q] = 0.f;
#pragma unroll
        for (int ks = 0; ks < 4; ks++) {
#pragma unroll
            for (int jp = 0; jp < 4; jp++) {
                uint32_t kaddr = KT + laneB + jp * 16 * AT_ROW + ks * 32;
                uint32_t rh[4], rl[4];
                LDSM4(rh, kaddr);
                LDSM4(rl, kaddr + AT_TILE);
#pragma unroll
                for (int t = 0; t < 2; t++) {
                    int j = 2 * jp + t;
                    mma16816(s[j], qh[ks], rh[2 * t], rh[2 * t + 1]);
                    mma16816(s[j], qh[ks], rl[2 * t], rl[2 * t + 1]);
                    mma16816(s[j], ql[ks], rh[2 * t], rh[2 * t + 1]);
                }
            }
        }

        const int k0 = c * 64;
#pragma unroll
        for (int j = 0; j < 8; j++)
#pragma unroll
            for (int q = 0; q < 4; q++) s[j][q] *= 0.125f;
        if (c >= jmax - 2) {
#pragma unroll
            for (int j = 0; j < 8; j++) {
                int col = k0 + 8 * j + 2 * tig;
                if (col > r0)          s[j][0] = -1e30f;
                if (col + 1 > r0)      s[j][1] = -1e30f;
                if (col > r0 + 8)      s[j][2] = -1e30f;
                if (col + 1 > r0 + 8)  s[j][3] = -1e30f;
            }
        }

        // ---- online softmax
        float pm0 = -1e30f, pm1 = -1e30f;
#pragma unroll
        for (int j = 0; j < 8; j++) {
            pm0 = fmaxf(pm0, fmaxf(s[j][0], s[j][1]));
            pm1 = fmaxf(pm1, fmaxf(s[j][2], s[j][3]));
        }
        pm0 = fmaxf(pm0, __shfl_xor_sync(0xffffffffu, pm0, 1));
        pm0 = fmaxf(pm0, __shfl_xor_sync(0xffffffffu, pm0, 2));
        pm1 = fmaxf(pm1, __shfl_xor_sync(0xffffffffu, pm1, 1));
        pm1 = fmaxf(pm1, __shfl_xor_sync(0xffffffffu, pm1, 2));
        float mn0 = fmaxf(mr0, pm0), mn1 = fmaxf(mr1, pm1);
        float a0 = __expf(mr0 - mn0), a1 = __expf(mr1 - mn1);
        float sum0 = 0.f, sum1 = 0.f;
#pragma unroll
        for (int j = 0; j < 8; j++) {
            s[j][0] = __expf(s[j][0] - mn0);
            s[j][1] = __expf(s[j][1] - mn0);
            s[j][2] = __expf(s[j][2] - mn1);
            s[j][3] = __expf(s[j][3] - mn1);
            sum0 += s[j][0] + s[j][1];
            sum1 += s[j][2] + s[j][3];
        }
        sum0 += __shfl_xor_sync(0xffffffffu, sum0, 1);
        sum0 += __shfl_xor_sync(0xffffffffu, sum0, 2);
        sum1 += __shfl_xor_sync(0xffffffffu, sum1, 1);
        sum1 += __shfl_xor_sync(0xffffffffu, sum1, 2);
        lr0 = lr0 * a0 + sum0;
        lr1 = lr1 * a1 + sum1;
        mr0 = mn0; mr1 = mn1;
#pragma unroll
        for (int j = 0; j < 8; j++) {
            oacc[j][0] *= a0; oacc[j][1] *= a0;
            oacc[j][2] *= a1; oacc[j][3] *= a1;
        }

        // ---- pack P fragments (bf16 hi/lo) from S accumulators
        uint32_t pah[4][4], pal[4][4];
#pragma unroll
        for (int ks = 0; ks < 4; ks++) {
            int j0 = 2 * ks, j1 = 2 * ks + 1;
#pragma unroll
            for (int part = 0; part < 4; part++) {
                int jj = (part < 2) ? j0 : j1;
                int qa = (part & 1) * 2;
                float x = s[jj][qa], y = s[jj][qa + 1];
                __nv_bfloat162 hp = __floats2bfloat162_rn(x, y);
                __nv_bfloat162 lp = __floats2bfloat162_rn(
                    x - __bfloat162float(hp.x), y - __bfloat162float(hp.y));
                pah[ks][part] = b2u(hp);
                pal[ks][part] = b2u(lp);
            }
        }

        // ---- O += P V (ph*vh + ph*vl + pl*vh)
#pragma unroll
        for (int ks = 0; ks < 4; ks++) {
#pragma unroll
            for (int jp = 0; jp < 4; jp++) {
                uint32_t vaddr = VT + laneB + jp * 16 * AT_ROW + ks * 32;
                uint32_t rh[4], rl[4];
                LDSM4(rh, vaddr);
                LDSM4(rl, vaddr + AT_TILE);
#pragma unroll
                for (int t = 0; t < 2; t++) {
                    int j = 2 * jp + t;
                    mma16816(oacc[j], pah[ks], rh[2 * t], rh[2 * t + 1]);
                    mma16816(oacc[j], pah[ks], rl[2 * t], rl[2 * t + 1]);
                    mma16816(oacc[j], pal[ks], rh[2 * t], rh[2 * t + 1]);
                }
            }
        }
        __syncthreads();
    }

    // ---- epilogue: normalize, split bf16, write g_ah/g_al [B,T,C]
    const int b = bh >> 4;
    const int h = bh & 15;
    float inv0 = 1.f / lr0, inv1 = 1.f / lr1;
#pragma unroll
    for (int j = 0; j < 8; j++) {
        int d = 8 * j + 2 * tig;
        size_t o0 = ((size_t)(b * TT + r0)) * CC + h * HD + d;
        size_t o1 = ((size_t)(b * TT + r0 + 8)) * CC + h * HD + d;
        float x0 = oacc[j][0] * inv0, y0 = oacc[j][1] * inv0;
        float x1 = oacc[j][2] * inv1, y1 = oacc[j][3] * inv1;
        __nv_bfloat162 h0 = __floats2bfloat162_rn(x0, y0);
        __nv_bfloat162 l0 = __floats2bfloat162_rn(x0 - __bfloat162float(h0.x),
                                                  y0 - __bfloat162float(h0.y));
        __nv_bfloat162 h1 = __floats2bfloat162_rn(x1, y1);
        __nv_bfloat162 l1 = __floats2bfloat162_rn(x1 - __bfloat162float(h1.x),
                                                  y1 - __bfloat162float(h1.y));
        *(__nv_bfloat162*)(g_ah + o0) = h0;
        *(__nv_bfloat162*)(g_al + o0) = l0;
        *(__nv_bfloat162*)(g_ah + o1) = h1;
        *(__nv_bfloat162*)(g_al + o1) = l1;
    }
}

// ---------------------------------------------------------------------------

extern "C" void kernel_launch(void* const* d_in, const int* in_sizes, int n_in,
                              void* d_out, int out_size) {
    const float* x      = (const float*)d_in[0];
    const float* w_qkv  = (const float*)d_in[1];
    const float* w_proj = (const float*)d_in[2];
    const float* b_proj = (const float*)d_in[3];
    float* out = (float*)d_out;

    __nv_bfloat16 *xh, *xl, *wqh, *wql, *wph, *wpl, *ah, *al;
    cudaGetSymbolAddress((void**)&xh,  g_xh);
    cudaGetSymbolAddress((void**)&xl,  g_xl);
    cudaGetSymbolAddress((void**)&wqh, g_wqh);
    cudaGetSymbolAddress((void**)&wql, g_wql);
    cudaGetSymbolAddress((void**)&wph, g_wph);
    cudaGetSymbolAddress((void**)&wpl, g_wpl);
    cudaGetSymbolAddress((void**)&ah,  g_ah);
    cudaGetSymbolAddress((void**)&al,  g_al);

    cudaFuncSetAttribute(tc_gemm<0>, cudaFuncAttributeMaxDynamicSharedMemorySize, GEMM_SMEM);
    cudaFuncSetAttribute(tc_gemm<1>, cudaFuncAttributeMaxDynamicSharedMemorySize, GEMM_SMEM);
    cudaFuncSetAttribute(attn_kernel, cudaFuncAttributeMaxDynamicSharedMemorySize, ATT_SMEM_BYTES);

    split_kernel<<<2048, 256>>>(x, xh, xl, MROWS * CC / 4);
    split_kernel<<<2048, 256>>>(w_qkv, wqh, wql, N_QKV * CC / 4);
    split_kernel<<<1024, 256>>>(w_proj, wph, wpl, CC * CC / 4);

    tc_gemm<0><<<dim3(N_QKV / 128, MROWS / 128), 256, GEMM_SMEM>>>(
        xh, xl, wqh, wql, nullptr, nullptr);
    attn_kernel<<<dim3(TT / 128, BB * HH), 256, ATT_SMEM_BYTES>>>();
    tc_gemm<1><<<dim3(CC / 128, MROWS / 128), 256, GEMM_SMEM>>>(
        ah, al, wph, wpl, b_proj, out);
}